// round 7
// baseline (speedup 1.0000x reference)
#include <cuda_runtime.h>
#include <math.h>

// StatefulSynapseNet, R7: R6 (dual-sample warp, const weights, f32x2 FFMA)
// with weight operands SPLIT across ports: o in [0,16) from __constant__
// (LDC), o in [16,32) from block-staged shared (broadcast LDS.128). Halves
// constant-port pressure if GPR-dest LDC (floor 8/SMSP) was pacing.

typedef unsigned long long ull;

__device__ __forceinline__ ull pack2(float lo, float hi) {
    ull r; asm("mov.b64 %0, {%1,%2};" : "=l"(r) : "f"(lo), "f"(hi)); return r;
}
__device__ __forceinline__ void unpack2(ull v, float& lo, float& hi) {
    asm("mov.b64 {%0,%1}, %2;" : "=f"(lo), "=f"(hi) : "l"(v));
}
__device__ __forceinline__ ull ffma2(ull a, ull b, ull c) {
    ull d; asm("fma.rn.f32x2 %0, %1, %2, %3;" : "=l"(d) : "l"(a), "l"(b), "l"(c)); return d;
}

#define T_DIM 28
#define F_DIM 28
#define C1 32
#define C2 10
#define WARPS 4
#define SPW 2
#define HP 33
#define H2P 29
#define REGION (T_DIM*HP + C2*H2P + 2)   // 1216 floats per sample

// constant block: lower halves (o<16) + biases
#define OFF_W1T 0          // [f*16 + o], o in [0,16): W1[o*28+f]
#define OFF_W2  448        // [j*16 + o], o in [0,16)
#define OFF_B1  608
#define OFF_B2  640
#define OFF_ITAU 650
#define CP_SIZE 652

// global stage: upper halves (o>=16) for shared
#define GS_W1H 0           // [f*16 + (o-16)]
#define GS_W2H 448         // [j*16 + (o-16)]
#define GS_SIZE 608

__constant__ __align__(16) float c_P[CP_SIZE];
__device__   __align__(16) float g_cstage[CP_SIZE];
__device__   __align__(16) float g_shalf[GS_SIZE];

__global__ void setup_kernel(const float* __restrict__ W1,
                             const float* __restrict__ b1,
                             const float* __restrict__ w_syn,
                             const float* __restrict__ W2,
                             const float* __restrict__ b2)
{
    int i = threadIdx.x;
    for (int idx = i; idx < F_DIM * 16; idx += 1024) {
        int f = idx >> 4, o = idx & 15;
        g_cstage[OFF_W1T + idx] = W1[o * F_DIM + f];          // o in [0,16)
        g_shalf[GS_W1H + idx]   = W1[(o + 16) * F_DIM + f];   // o in [16,32)
    }
    for (int idx = i; idx < C2 * 16; idx += 1024) {
        int j = idx >> 4, o = idx & 15;
        g_cstage[OFF_W2 + idx] = W2[j * C1 + o];
        g_shalf[GS_W2H + idx]  = W2[j * C1 + o + 16];
    }
    if (i < C1) g_cstage[OFF_B1 + i] = b1[i];
    if (i < C2) g_cstage[OFF_B2 + i] = b2[i];
    if (i == 0) g_cstage[OFF_ITAU] = 1.0f / (1.0f + expf(-w_syn[0]));
}

__global__ __launch_bounds__(WARPS * 32, 5)
void snn_kernel(const float* __restrict__ x, float* __restrict__ out, int N)
{
    __shared__ float sh[WARPS * SPW * REGION];
    __shared__ __align__(16) float sh_wh[GS_SIZE];     // upper-half weights

    const int lane = threadIdx.x & 31;
    const int warp = threadIdx.x >> 5;

    // stage upper-half weights once per block (coalesced float4)
    for (int i = threadIdx.x; i < GS_SIZE / 4; i += WARPS * 32)
        reinterpret_cast<float4*>(sh_wh)[i] = reinterpret_cast<const float4*>(g_shalf)[i];
    __syncthreads();

    const int n0 = (blockIdx.x * WARPS + warp) * SPW;
    if (n0 >= N) return;
    const bool has_b = (n0 + 1 < N);
    const int n1 = has_b ? (n0 + 1) : n0;

    float* shA = sh + warp * (SPW * REGION);
    float* shB = shA + REGION;
    float* sh2A = shA + T_DIM * HP;
    float* sh2B = shB + T_DIM * HP;
    const bool tl = (lane < T_DIM);

    // ---- phase 1: lane = t; dual-sample accumulators, split-port weights ----
    ull accA[C1 / 2], accB[C1 / 2];
#pragma unroll
    for (int p = 0; p < C1 / 2; ++p) {
        ull b = *reinterpret_cast<const ull*>(c_P + OFF_B1 + 2 * p);
        accA[p] = b; accB[p] = b;
    }

    const float* xa = x + (size_t)n0 * (F_DIM * T_DIM) + lane;
    const float* xb = x + (size_t)n1 * (F_DIM * T_DIM) + lane;
#pragma unroll 4
    for (int f = 0; f < F_DIM; ++f) {
        float xva = tl ? __ldg(xa + f * T_DIM) : 0.0f;
        float xvb = tl ? __ldg(xb + f * T_DIM) : 0.0f;
        ull xpa = pack2(xva, xva);
        ull xpb = pack2(xvb, xvb);
        const ulonglong2* wc = reinterpret_cast<const ulonglong2*>(c_P + OFF_W1T + f * 16);
        const ulonglong2* ws = reinterpret_cast<const ulonglong2*>(sh_wh + GS_W1H + f * 16);
#pragma unroll
        for (int q = 0; q < 4; ++q) {           // const port: o = 4q..4q+3
            ulonglong2 w = wc[q];
            accA[2 * q]     = ffma2(xpa, w.x, accA[2 * q]);
            accB[2 * q]     = ffma2(xpb, w.x, accB[2 * q]);
            accA[2 * q + 1] = ffma2(xpa, w.y, accA[2 * q + 1]);
            accB[2 * q + 1] = ffma2(xpb, w.y, accB[2 * q + 1]);
        }
#pragma unroll
        for (int q = 0; q < 4; ++q) {           // shared port: o = 16+4q..
            ulonglong2 w = ws[q];
            accA[8 + 2 * q] = ffma2(xpa, w.x, accA[8 + 2 * q]);
            accB[8 + 2 * q] = ffma2(xpb, w.x, accB[8 + 2 * q]);
            accA[9 + 2 * q] = ffma2(xpa, w.y, accA[9 + 2 * q]);
            accB[9 + 2 * q] = ffma2(xpb, w.y, accB[9 + 2 * q]);
        }
    }
    // transpose H to shared (scalar pitch-33, R4-proven)
    if (tl) {
#pragma unroll
        for (int p = 0; p < C1 / 2; ++p) {
            float a0, a1, b0, b1v;
            unpack2(accA[p], a0, a1);
            unpack2(accB[p], b0, b1v);
            shA[lane * HP + 2 * p]     = a0;
            shA[lane * HP + 2 * p + 1] = a1;
            shB[lane * HP + 2 * p]     = b0;
            shB[lane * HP + 2 * p + 1] = b1v;
        }
    }
    __syncwarp();

    // ---- IF scan + synapse filter: lane = o, both samples interleaved ----
    {
        const float itau = c_P[OFF_ITAU];
        float va = 0.0f, ga = 0.0f, vb = 0.0f, gb = 0.0f;
#pragma unroll
        for (int t = 0; t < T_DIM; ++t) {
            float ha = shA[t * HP + lane];
            float hb = shB[t * HP + lane];
            va += ha;                          vb += hb;
            bool sa = (va >= 1.0f);            bool sb = (vb >= 1.0f);
            va = sa ? 0.0f : va;               vb = sb ? 0.0f : vb;
            ga = fmaf(ga, -itau, ga) + (sa ? 1.0f : 0.0f);
            gb = fmaf(gb, -itau, gb) + (sb ? 1.0f : 0.0f);
            shA[t * HP + lane] = ga;
            shB[t * HP + lane] = gb;
        }
    }
    __syncwarp();

    // ---- phase 2: lane = t; W2 split across const + shared ----
    if (tl) {
        ull yqa[C1 / 2], yqb[C1 / 2];
        const float* ya = shA + lane * HP;
        const float* yb = shB + lane * HP;
#pragma unroll
        for (int q = 0; q < C1 / 2; ++q) {
            yqa[q] = pack2(ya[2 * q], ya[2 * q + 1]);
            yqb[q] = pack2(yb[2 * q], yb[2 * q + 1]);
        }
#pragma unroll
        for (int j = 0; j < C2; ++j) {
            ull a2 = 0ULL, b2a = 0ULL;
            const ulonglong2* wc = reinterpret_cast<const ulonglong2*>(c_P + OFF_W2 + j * 16);
            const ulonglong2* ws = reinterpret_cast<const ulonglong2*>(sh_wh + GS_W2H + j * 16);
#pragma unroll
            for (int q = 0; q < 4; ++q) {       // o = 4q..4q+3 (const)
                ulonglong2 w = wc[q];
                a2  = ffma2(yqa[2 * q],     w.x, a2);
                b2a = ffma2(yqb[2 * q],     w.x, b2a);
                a2  = ffma2(yqa[2 * q + 1], w.y, a2);
                b2a = ffma2(yqb[2 * q + 1], w.y, b2a);
            }
#pragma unroll
            for (int q = 0; q < 4; ++q) {       // o = 16+4q.. (shared)
                ulonglong2 w = ws[q];
                a2  = ffma2(yqa[8 + 2 * q], w.x, a2);
                b2a = ffma2(yqb[8 + 2 * q], w.x, b2a);
                a2  = ffma2(yqa[9 + 2 * q], w.y, a2);
                b2a = ffma2(yqb[9 + 2 * q], w.y, b2a);
            }
            float u0, u1, v0, v1;
            unpack2(a2, u0, u1);
            unpack2(b2a, v0, v1);
            float bj = c_P[OFF_B2 + j];
            sh2A[j * H2P + lane] = u0 + u1 + bj;
            sh2B[j * H2P + lane] = v0 + v1 + bj;
        }
    }
    __syncwarp();

    // ---- second IF scan + mean: 20 lanes (j = lane&15, sample = lane>>4) ----
    {
        int sj = lane & 15;
        int ss = lane >> 4;
        if (sj < C2 && (ss == 0 || has_b)) {
            const float* h2 = ss ? sh2B : sh2A;
            float v = 0.0f, cnt = 0.0f;
#pragma unroll
            for (int t = 0; t < T_DIM; ++t) {
                v += h2[sj * H2P + t];
                if (v >= 1.0f) { cnt += 1.0f; v = 0.0f; }
            }
            int nn = ss ? n1 : n0;
            out[(size_t)nn * C2 + sj] = cnt * (1.0f / 28.0f);
        }
    }
}

extern "C" void kernel_launch(void* const* d_in, const int* in_sizes, int n_in,
                              void* d_out, int out_size)
{
    const float* x     = (const float*)d_in[0];
    const float* W1    = (const float*)d_in[1];
    const float* b1    = (const float*)d_in[2];
    const float* w_syn = (const float*)d_in[3];
    const float* W2    = (const float*)d_in[4];
    const float* b2    = (const float*)d_in[5];
    float* out = (float*)d_out;

    const int N = in_sizes[0] / (F_DIM * T_DIM);

    setup_kernel<<<1, 1024>>>(W1, b1, w_syn, W2, b2);

    void* sp = nullptr;
    cudaGetSymbolAddress(&sp, g_cstage);
    cudaMemcpyToSymbolAsync(c_P, sp, CP_SIZE * sizeof(float), 0,
                            cudaMemcpyDeviceToDevice, 0);

    const int spb = WARPS * SPW;
    const int blocks = (N + spb - 1) / spb;
    snn_kernel<<<blocks, WARPS * 32>>>(x, out, N);
}

// round 8
// speedup vs baseline: 1.3594x; 1.3594x over previous
#include <cuda_runtime.h>
#include <math.h>

// StatefulSynapseNet, R8: R6 structure (dual-sample warp, ALL weights via
// __constant__, f32x2 FFMA, scalar pitch-33 transposes) with both GEMMs
// split into two o-halves to halve accumulator registers, h2 overlaid on the
// y region, unroll-7 x loads. Goal: 7 blocks/SM (44% occ) vs R6's 5 (28%).

typedef unsigned long long ull;

__device__ __forceinline__ ull pack2(float lo, float hi) {
    ull r; asm("mov.b64 %0, {%1,%2};" : "=l"(r) : "f"(lo), "f"(hi)); return r;
}
__device__ __forceinline__ void unpack2(ull v, float& lo, float& hi) {
    asm("mov.b64 {%0,%1}, %2;" : "=f"(lo), "=f"(hi) : "l"(v));
}
__device__ __forceinline__ ull ffma2(ull a, ull b, ull c) {
    ull d; asm("fma.rn.f32x2 %0, %1, %2, %3;" : "=l"(d) : "l"(a), "l"(b), "l"(c)); return d;
}

#define T_DIM 28
#define F_DIM 28
#define C1 32
#define C2 10
#define WARPS 4
#define SPW 2
#define HP 33              // H/y pitch, conflict-free scalar pattern (R4/R6-proven)
#define H2P 29
#define REGION 928         // 28*33 = 924 floats, padded to 16B multiple

// constant-block layout (floats) — identical to R6
#define OFF_W1T 0          // [f*32 + o] = W1[o*28+f]
#define OFF_W2  896        // [j*32 + o]
#define OFF_B1  1216
#define OFF_B2  1248
#define OFF_ITAU 1258
#define CP_SIZE 1280

__constant__ __align__(16) float c_P[CP_SIZE];
__device__   __align__(16) float g_stage[CP_SIZE];

__global__ void setup_kernel(const float* __restrict__ W1,
                             const float* __restrict__ b1,
                             const float* __restrict__ w_syn,
                             const float* __restrict__ W2,
                             const float* __restrict__ b2)
{
    int i = threadIdx.x;
    for (int idx = i; idx < C1 * F_DIM; idx += 1024) {
        int f = idx >> 5, o = idx & 31;
        g_stage[OFF_W1T + idx] = W1[o * F_DIM + f];
    }
    for (int idx = i; idx < C2 * C1; idx += 1024)
        g_stage[OFF_W2 + idx] = W2[idx];
    if (i < C1) g_stage[OFF_B1 + i] = b1[i];
    if (i < C2) g_stage[OFF_B2 + i] = b2[i];
    if (i == 0) g_stage[OFF_ITAU] = 1.0f / (1.0f + expf(-w_syn[0]));
}

__global__ __launch_bounds__(WARPS * 32, 7)
void snn_kernel(const float* __restrict__ x, float* __restrict__ out, int N)
{
    __shared__ float sh[WARPS * SPW * REGION];
    const int lane = threadIdx.x & 31;
    const int warp = threadIdx.x >> 5;
    const int n0 = (blockIdx.x * WARPS + warp) * SPW;
    if (n0 >= N) return;
    const bool has_b = (n0 + 1 < N);
    const int n1 = has_b ? (n0 + 1) : n0;

    float* shA = sh + warp * (SPW * REGION);   // H/y [t][o] pitch 33; h2 overlays later
    float* shB = shA + REGION;
    const bool tl = (lane < T_DIM);

    const float* xa = x + (size_t)n0 * (F_DIM * T_DIM) + lane;
    const float* xb = x + (size_t)n1 * (F_DIM * T_DIM) + lane;

    // ---- phase 1: lane = t, two o-halves; acc = 8 ull per sample per half ----
#pragma unroll
    for (int half = 0; half < 2; ++half) {
        ull accA[8], accB[8];
#pragma unroll
        for (int p = 0; p < 8; ++p) {
            ull b = *reinterpret_cast<const ull*>(c_P + OFF_B1 + half * 16 + 2 * p);
            accA[p] = b; accB[p] = b;
        }
#pragma unroll 7
        for (int f = 0; f < F_DIM; ++f) {
            float xva = tl ? __ldg(xa + f * T_DIM) : 0.0f;
            float xvb = tl ? __ldg(xb + f * T_DIM) : 0.0f;
            ull xpa = pack2(xva, xva);
            ull xpb = pack2(xvb, xvb);
            const ulonglong2* wq =
                reinterpret_cast<const ulonglong2*>(c_P + OFF_W1T + f * C1 + half * 16);
#pragma unroll
            for (int q = 0; q < 4; ++q) {      // each const load feeds 4 FFMA2
                ulonglong2 w = wq[q];
                accA[2 * q]     = ffma2(xpa, w.x, accA[2 * q]);
                accB[2 * q]     = ffma2(xpb, w.x, accB[2 * q]);
                accA[2 * q + 1] = ffma2(xpa, w.y, accA[2 * q + 1]);
                accB[2 * q + 1] = ffma2(xpb, w.y, accB[2 * q + 1]);
            }
        }
        if (tl) {
#pragma unroll
            for (int p = 0; p < 8; ++p) {
                float a0, a1, b0, b1v;
                unpack2(accA[p], a0, a1);
                unpack2(accB[p], b0, b1v);
                shA[lane * HP + half * 16 + 2 * p]     = a0;
                shA[lane * HP + half * 16 + 2 * p + 1] = a1;
                shB[lane * HP + half * 16 + 2 * p]     = b0;
                shB[lane * HP + half * 16 + 2 * p + 1] = b1v;
            }
        }
    }
    __syncwarp();

    // ---- IF scan + synapse filter: lane = o, both samples interleaved ----
    {
        const float itau = c_P[OFF_ITAU];
        float va = 0.0f, ga = 0.0f, vb = 0.0f, gb = 0.0f;
#pragma unroll
        for (int t = 0; t < T_DIM; ++t) {
            float ha = shA[t * HP + lane];
            float hb = shB[t * HP + lane];
            va += ha;                          vb += hb;
            bool sa = (va >= 1.0f);            bool sb = (vb >= 1.0f);
            va = sa ? 0.0f : va;               vb = sb ? 0.0f : vb;
            ga = fmaf(ga, -itau, ga) + (sa ? 1.0f : 0.0f);
            gb = fmaf(gb, -itau, gb) + (sb ? 1.0f : 0.0f);
            shA[t * HP + lane] = ga;
            shB[t * HP + lane] = gb;
        }
    }
    __syncwarp();

    // ---- phase 2: lane = t, two o-halves, scalar partials; h2 overlays y ----
    {
        float pA[C2], pB[C2];
#pragma unroll
        for (int j = 0; j < C2; ++j) { pA[j] = 0.0f; pB[j] = 0.0f; }

        if (tl) {
#pragma unroll
            for (int half = 0; half < 2; ++half) {
                ull yqa[8], yqb[8];
                const float* ya = shA + lane * HP + half * 16;
                const float* yb = shB + lane * HP + half * 16;
#pragma unroll
                for (int q = 0; q < 8; ++q) {
                    yqa[q] = pack2(ya[2 * q], ya[2 * q + 1]);
                    yqb[q] = pack2(yb[2 * q], yb[2 * q + 1]);
                }
#pragma unroll
                for (int j = 0; j < C2; ++j) {
                    ull a2 = 0ULL, b2a = 0ULL;
                    const ulonglong2* wq2 =
                        reinterpret_cast<const ulonglong2*>(c_P + OFF_W2 + j * C1 + half * 16);
#pragma unroll
                    for (int q = 0; q < 4; ++q) {
                        ulonglong2 w = wq2[q];
                        a2  = ffma2(yqa[2 * q],     w.x, a2);
                        b2a = ffma2(yqb[2 * q],     w.x, b2a);
                        a2  = ffma2(yqa[2 * q + 1], w.y, a2);
                        b2a = ffma2(yqb[2 * q + 1], w.y, b2a);
                    }
                    float u0, u1, v0, v1;
                    unpack2(a2, u0, u1);
                    unpack2(b2a, v0, v1);
                    pA[j] += u0 + u1;
                    pB[j] += v0 + v1;
                }
            }
        }
        __syncwarp();                          // all y reads done -> overlay h2

        if (tl) {
#pragma unroll
            for (int j = 0; j < C2; ++j) {
                float bj = c_P[OFF_B2 + j];
                shA[j * H2P + lane] = pA[j] + bj;   // h2 overlays y region
                shB[j * H2P + lane] = pB[j] + bj;
            }
        }
    }
    __syncwarp();

    // ---- second IF scan + mean: 20 lanes (j = lane&15, sample = lane>>4) ----
    {
        int sj = lane & 15;
        int ss = lane >> 4;
        if (sj < C2 && (ss == 0 || has_b)) {
            const float* h2 = ss ? shB : shA;
            float v = 0.0f, cnt = 0.0f;
#pragma unroll
            for (int t = 0; t < T_DIM; ++t) {
                v += h2[sj * H2P + t];
                if (v >= 1.0f) { cnt += 1.0f; v = 0.0f; }
            }
            int nn = ss ? n1 : n0;
            out[(size_t)nn * C2 + sj] = cnt * (1.0f / 28.0f);
        }
    }
}

extern "C" void kernel_launch(void* const* d_in, const int* in_sizes, int n_in,
                              void* d_out, int out_size)
{
    const float* x     = (const float*)d_in[0];
    const float* W1    = (const float*)d_in[1];
    const float* b1    = (const float*)d_in[2];
    const float* w_syn = (const float*)d_in[3];
    const float* W2    = (const float*)d_in[4];
    const float* b2    = (const float*)d_in[5];
    float* out = (float*)d_out;

    const int N = in_sizes[0] / (F_DIM * T_DIM);

    setup_kernel<<<1, 1024>>>(W1, b1, w_syn, W2, b2);

    void* sp = nullptr;
    cudaGetSymbolAddress(&sp, g_stage);
    cudaMemcpyToSymbolAsync(c_P, sp, CP_SIZE * sizeof(float), 0,
                            cudaMemcpyDeviceToDevice, 0);

    const int spb = WARPS * SPW;
    const int blocks = (N + spb - 1) / spb;
    snn_kernel<<<blocks, WARPS * 32>>>(x, out, N);
}